// round 10
// baseline (speedup 1.0000x reference)
#include <cuda_runtime.h>
#include <math.h>

// Problem constants
#define BB   256      // batch
#define SS   512      // seq
#define DD   256      // feature dim (K of GEMM)
#define AT   128      // attention dim (N of GEMM)

// GEMM tiling
#define TM   128      // rows per block (within one batch: 512/128 = 4 blocks/batch)
#define TN   128      // cols per block (= AT, full)
#define BK   32       // K chunk
#define BKP  33       // padded A row stride (conflict-free column reads)
#define NTHREADS 256  // 16x16 thread grid, 8x8 register tile each

// Scratch (no allocation allowed -> device global)
__device__ float g_scores[BB * SS];   // e = exp(z) per (b,s)

// Packed fp32x2 FMA: d = a*b + d per 32-bit lane (Blackwell double-rate fp32).
#define FFMA2(d, a, b) \
    asm("fma.rn.f32x2 %0, %1, %2, %0;" : "+l"(d) : "l"(a), "l"(b))

// Fused: z[b,s] = sum_a u[a] * tanh( (x@W)[b,s,a] + bias[a] );  e = exp(z)
// One block computes a 128-row x 128-col tile of x@W, mainloop on fp32x2
// packed FMA (2 cols per accumulator), register-prefetch pipelined.
__global__ void __launch_bounds__(NTHREADS, 2)
scores_kernel(const float* __restrict__ x,
              const float* __restrict__ W,
              const float* __restrict__ bias,
              const float* __restrict__ u)
{
    __shared__ float As[TM][BKP];   // x chunk, row-major, padded
    __shared__ float Bs[BK][TN];    // W chunk, row-major

    const int tid = threadIdx.x;
    const int tx  = tid & 15;       // col group 0..15
    const int ty  = tid >> 4;       // row group 0..15
    const int row0 = ty * 8;
    const int col0 = tx * 8;
    const int m0 = blockIdx.x * TM; // global row into x viewed as [B*S, D]

    // Per-thread load slots: A chunk = TM*BK/4 = 1024 float4 / 256 thr = 4 each,
    // B chunk = BK*TN/4 = 1024 float4 / 256 thr = 4 each.
    const int a_r [4] = { (tid + 0*NTHREADS) >> 3, (tid + 1*NTHREADS) >> 3,
                          (tid + 2*NTHREADS) >> 3, (tid + 3*NTHREADS) >> 3 };
    const int a_c4[4] = { ((tid + 0*NTHREADS) & 7) * 4, ((tid + 1*NTHREADS) & 7) * 4,
                          ((tid + 2*NTHREADS) & 7) * 4, ((tid + 3*NTHREADS) & 7) * 4 };
    const int b_r [4] = { (tid + 0*NTHREADS) >> 5, (tid + 1*NTHREADS) >> 5,
                          (tid + 2*NTHREADS) >> 5, (tid + 3*NTHREADS) >> 5 };
    const int b_n4[4] = { ((tid + 0*NTHREADS) & 31) * 4, ((tid + 1*NTHREADS) & 31) * 4,
                          ((tid + 2*NTHREADS) & 31) * 4, ((tid + 3*NTHREADS) & 31) * 4 };

    float4 ar[4], br[4];

    // Preload chunk 0
    #pragma unroll
    for (int i = 0; i < 4; i++) {
        ar[i] = *reinterpret_cast<const float4*>(
            &x[(size_t)(m0 + a_r[i]) * DD + 0 + a_c4[i]]);
        br[i] = *reinterpret_cast<const float4*>(
            &W[(size_t)(0 + b_r[i]) * AT + b_n4[i]]);
    }

    // Accumulators: 8 rows x 4 packed col-pairs (cols col0+2j, col0+2j+1)
    unsigned long long acc2[8][4];
    #pragma unroll
    for (int i = 0; i < 8; i++)
        #pragma unroll
        for (int j = 0; j < 4; j++) acc2[i][j] = 0ULL;  // (0.0f, 0.0f)

    for (int k0 = 0; k0 < DD; k0 += BK) {
        // Commit prefetched registers to smem
        #pragma unroll
        for (int i = 0; i < 4; i++) {
            As[a_r[i]][a_c4[i] + 0] = ar[i].x;
            As[a_r[i]][a_c4[i] + 1] = ar[i].y;
            As[a_r[i]][a_c4[i] + 2] = ar[i].z;
            As[a_r[i]][a_c4[i] + 3] = ar[i].w;
            *reinterpret_cast<float4*>(&Bs[b_r[i]][b_n4[i]]) = br[i];
        }
        __syncthreads();

        // Prefetch next chunk (overlaps with the FMA block below)
        if (k0 + BK < DD) {
            const int kn = k0 + BK;
            #pragma unroll
            for (int i = 0; i < 4; i++) {
                ar[i] = *reinterpret_cast<const float4*>(
                    &x[(size_t)(m0 + a_r[i]) * DD + kn + a_c4[i]]);
                br[i] = *reinterpret_cast<const float4*>(
                    &W[(size_t)(kn + b_r[i]) * AT + b_n4[i]]);
            }
        }

        #pragma unroll
        for (int kk = 0; kk < BK; kk++) {
            // A values: 16-lane broadcast scalar loads, duplicated into f32x2
            unsigned long long a2[8];
            #pragma unroll
            for (int i = 0; i < 8; i++) {
                unsigned int au = __float_as_uint(As[row0 + i][kk]);
                asm("mov.b64 %0, {%1, %1};" : "=l"(a2[i]) : "r"(au));
            }
            // B pairs: adjacent floats in smem ARE the packed operand (LDS.64)
            const unsigned long long* bp =
                reinterpret_cast<const unsigned long long*>(&Bs[kk][col0]);
            unsigned long long b2[4];
            #pragma unroll
            for (int j = 0; j < 4; j++) b2[j] = bp[j];

            #pragma unroll
            for (int i = 0; i < 8; i++)
                #pragma unroll
                for (int j = 0; j < 4; j++)
                    FFMA2(acc2[i][j], a2[i], b2[j]);
        }
        __syncthreads();   // smem free for next chunk's commit
    }

    // Unpack accumulators to scalar grid (col = col0 + 2*j + lane)
    float accf[8][8];
    #pragma unroll
    for (int i = 0; i < 8; i++)
        #pragma unroll
        for (int j = 0; j < 4; j++) {
            unsigned int lo, hi;
            asm("mov.b64 {%0, %1}, %2;" : "=r"(lo), "=r"(hi) : "l"(acc2[i][j]));
            accf[i][2*j + 0] = __uint_as_float(lo);
            accf[i][2*j + 1] = __uint_as_float(hi);
        }

    // Epilogue: bias -> tanh -> dot with u -> reduce across the 16 col-groups
    float zp[8];
    #pragma unroll
    for (int i = 0; i < 8; i++) zp[i] = 0.0f;
    #pragma unroll
    for (int j = 0; j < 8; j++) {
        float bj = bias[col0 + j];
        float uj = u[col0 + j];
        #pragma unroll
        for (int i = 0; i < 8; i++) {
            zp[i] += uj * tanhf(accf[i][j] + bj);
        }
    }
    // Reduce over tx (lane = ty*16 + tx; xor 8,4,2,1 stays within the 16-lane group)
    #pragma unroll
    for (int i = 0; i < 8; i++) {
        #pragma unroll
        for (int off = 8; off >= 1; off >>= 1)
            zp[i] += __shfl_xor_sync(0xFFFFFFFFu, zp[i], off, 32);
    }

    if (tx == 0) {
        #pragma unroll
        for (int i = 0; i < 8; i++) {
            int m = m0 + row0 + i;                // global row in [B*S]
            g_scores[m] = expf(zp[i]);            // faithful: no max-subtraction
        }
    }
}

// out[b,d] = sum_s x[b,s,d] * e[b,s] / (sum_s e[b,s] + 1e-8)
// Denominator computed here (deterministic block reduction, no atomics).
__global__ void __launch_bounds__(256, 4)
output_kernel(const float* __restrict__ x, float* __restrict__ out)
{
    __shared__ float w[SS];
    __shared__ float red[8];
    const int b = blockIdx.x;
    const int t = threadIdx.x;                    // 256 threads = one per d

    // Stage scores and reduce the denominator
    float e0 = g_scores[b * SS + t];
    float e1 = g_scores[b * SS + 256 + t];
    w[t]       = e0;
    w[256 + t] = e1;
    float part = e0 + e1;
    #pragma unroll
    for (int off = 16; off >= 1; off >>= 1)
        part += __shfl_xor_sync(0xFFFFFFFFu, part, off, 32);
    if ((t & 31) == 0) red[t >> 5] = part;
    __syncthreads();
    float denom = red[0] + red[1] + red[2] + red[3]
                + red[4] + red[5] + red[6] + red[7];
    float inv = 1.0f / (denom + 1e-8f);
    __syncthreads();

    const float* xb = x + (size_t)b * SS * DD;
    float acc = 0.0f;
    #pragma unroll 8
    for (int s = 0; s < SS; s++)
        acc = fmaf(xb[(size_t)s * DD + t], w[s], acc);
    out[b * DD + t] = acc * inv;
}

extern "C" void kernel_launch(void* const* d_in, const int* in_sizes, int n_in,
                              void* d_out, int out_size)
{
    const float* x    = (const float*)d_in[0];   // [B,S,D]
    const float* W    = (const float*)d_in[1];   // [D,AT]
    const float* bias = (const float*)d_in[2];   // [AT]
    const float* u    = (const float*)d_in[3];   // [AT,1]
    float* out        = (float*)d_out;           // [B,D]

    (void)in_sizes; (void)n_in; (void)out_size;

    scores_kernel<<<(BB * SS) / TM, NTHREADS>>>(x, W, bias, u);
    output_kernel<<<BB, 256>>>(x, out);
}

// round 13
// speedup vs baseline: 1.1317x; 1.1317x over previous
#include <cuda_runtime.h>
#include <math.h>

// Problem constants
#define BB   256      // batch
#define SS   512      // seq
#define DD   256      // feature dim (K of GEMM)
#define AT   128      // attention dim (N of GEMM)

// GEMM tiling
#define TM   128      // rows per block
#define TN   128      // cols per block (= AT, full)
#define BK   32       // K chunk
#define BKP  33       // padded A row stride
#define NTHREADS 256  // 16x16 thread grid, 8x8 register tile each

// Scratch (no allocation allowed -> device globals)
__device__ float g_scores[BB * SS];        // e = exp(z) per (b,s)
__device__ float g_part[BB * 2 * DD];      // per-half weighted sums

// Packed fp32x2 FMA: d = a*b + d per 32-bit lane.
#define FFMA2(d, a, b) \
    asm("fma.rn.f32x2 %0, %1, %2, %0;" : "+l"(d) : "l"(a), "l"(b))

// Fused scores: z[b,s] = sum_a u[a] * tanh((x@W)[b,s,a] + b[a]); e = exp(z).
// fp32x2 mainloop. Per-thread columns are {2tx+32p, 2tx+1+32p}, p=0..3:
// LDS.64 of B pairs is bank-conflict-free (bank = 2tx mod 32, all distinct).
__global__ void __launch_bounds__(NTHREADS, 2)
scores_kernel(const float* __restrict__ x,
              const float* __restrict__ W,
              const float* __restrict__ bias,
              const float* __restrict__ u)
{
    __shared__ float As[TM][BKP];   // x chunk, padded
    __shared__ float Bs[BK][TN];    // W chunk

    const int tid = threadIdx.x;
    const int tx  = tid & 15;
    const int ty  = tid >> 4;
    const int row0 = ty * 8;
    const int m0 = blockIdx.x * TM;

    // Per-thread load slots (4 float4 each for A and B chunks)
    const int a_r [4] = { (tid + 0*NTHREADS) >> 3, (tid + 1*NTHREADS) >> 3,
                          (tid + 2*NTHREADS) >> 3, (tid + 3*NTHREADS) >> 3 };
    const int a_c4[4] = { ((tid + 0*NTHREADS) & 7) * 4, ((tid + 1*NTHREADS) & 7) * 4,
                          ((tid + 2*NTHREADS) & 7) * 4, ((tid + 3*NTHREADS) & 7) * 4 };
    const int b_r [4] = { (tid + 0*NTHREADS) >> 5, (tid + 1*NTHREADS) >> 5,
                          (tid + 2*NTHREADS) >> 5, (tid + 3*NTHREADS) >> 5 };
    const int b_n4[4] = { ((tid + 0*NTHREADS) & 31) * 4, ((tid + 1*NTHREADS) & 31) * 4,
                          ((tid + 2*NTHREADS) & 31) * 4, ((tid + 3*NTHREADS) & 31) * 4 };

    float4 ar[4], br[4];
    #pragma unroll
    for (int i = 0; i < 4; i++) {
        ar[i] = *reinterpret_cast<const float4*>(
            &x[(size_t)(m0 + a_r[i]) * DD + a_c4[i]]);
        br[i] = *reinterpret_cast<const float4*>(
            &W[(size_t)b_r[i] * AT + b_n4[i]]);
    }

    // Accumulators: 8 rows x 4 packed col-pairs; pair p covers cols (2tx+32p, +1)
    unsigned long long acc2[8][4];
    #pragma unroll
    for (int i = 0; i < 8; i++)
        #pragma unroll
        for (int j = 0; j < 4; j++) acc2[i][j] = 0ULL;

    for (int k0 = 0; k0 < DD; k0 += BK) {
        #pragma unroll
        for (int i = 0; i < 4; i++) {
            As[a_r[i]][a_c4[i] + 0] = ar[i].x;
            As[a_r[i]][a_c4[i] + 1] = ar[i].y;
            As[a_r[i]][a_c4[i] + 2] = ar[i].z;
            As[a_r[i]][a_c4[i] + 3] = ar[i].w;
            *reinterpret_cast<float4*>(&Bs[b_r[i]][b_n4[i]]) = br[i];
        }
        __syncthreads();

        if (k0 + BK < DD) {
            const int kn = k0 + BK;
            #pragma unroll
            for (int i = 0; i < 4; i++) {
                ar[i] = *reinterpret_cast<const float4*>(
                    &x[(size_t)(m0 + a_r[i]) * DD + kn + a_c4[i]]);
                br[i] = *reinterpret_cast<const float4*>(
                    &W[(size_t)(kn + b_r[i]) * AT + b_n4[i]]);
            }
        }

        #pragma unroll
        for (int kk = 0; kk < BK; kk++) {
            unsigned long long a2[8];
            #pragma unroll
            for (int i = 0; i < 8; i++) {
                unsigned int au = __float_as_uint(As[row0 + i][kk]);
                asm("mov.b64 %0, {%1, %1};" : "=l"(a2[i]) : "r"(au));
            }
            unsigned long long b2[4];
            #pragma unroll
            for (int p = 0; p < 4; p++)
                b2[p] = *reinterpret_cast<const unsigned long long*>(
                    &Bs[kk][2 * tx + 32 * p]);   // conflict-free LDS.64

            #pragma unroll
            for (int i = 0; i < 8; i++)
                #pragma unroll
                for (int p = 0; p < 4; p++)
                    FFMA2(acc2[i][p], a2[i], b2[p]);
        }
        __syncthreads();
    }

    // Epilogue: bias -> tanh -> dot u, on cols (2tx+32p, 2tx+1+32p)
    float zp[8];
    #pragma unroll
    for (int i = 0; i < 8; i++) zp[i] = 0.0f;
    #pragma unroll
    for (int p = 0; p < 4; p++) {
        const int c0 = 2 * tx + 32 * p;
        const float b0 = bias[c0],  b1 = bias[c0 + 1];
        const float u0 = u[c0],     u1 = u[c0 + 1];
        #pragma unroll
        for (int i = 0; i < 8; i++) {
            unsigned int lo, hi;
            asm("mov.b64 {%0, %1}, %2;" : "=r"(lo), "=r"(hi) : "l"(acc2[i][p]));
            zp[i] += u0 * tanhf(__uint_as_float(lo) + b0);
            zp[i] += u1 * tanhf(__uint_as_float(hi) + b1);
        }
    }
    // Reduce over the 16 tx lanes (xor 8,4,2,1 stays within each half-warp)
    #pragma unroll
    for (int i = 0; i < 8; i++) {
        #pragma unroll
        for (int off = 8; off >= 1; off >>= 1)
            zp[i] += __shfl_xor_sync(0xFFFFFFFFu, zp[i], off, 32);
    }
    if (tx == 0) {
        #pragma unroll
        for (int i = 0; i < 8; i++)
            g_scores[m0 + row0 + i] = expf(zp[i]);   // faithful: no max-subtraction
    }
}

// Partial weighted sums: block (b, h) handles s in [h*256, h*256+256).
// 512 blocks -> ~3.5 CTAs/SM; 4 independent accumulators for MLP.
__global__ void __launch_bounds__(256, 6)
output_partial_kernel(const float* __restrict__ x)
{
    __shared__ float w[SS / 2];
    __shared__ float red[8];
    const int b = blockIdx.x >> 1;
    const int h = blockIdx.x & 1;
    const int t = threadIdx.x;

    // Denominator over all 512 scores (cheap), weights for this half
    float eh = g_scores[b * SS + h * 256 + t];
    float eo = g_scores[b * SS + (1 - h) * 256 + t];
    w[t] = eh;
    float part = eh + eo;
    #pragma unroll
    for (int off = 16; off >= 1; off >>= 1)
        part += __shfl_xor_sync(0xFFFFFFFFu, part, off, 32);
    if ((t & 31) == 0) red[t >> 5] = part;
    __syncthreads();
    float denom = red[0] + red[1] + red[2] + red[3]
                + red[4] + red[5] + red[6] + red[7];
    float inv = 1.0f / (denom + 1e-8f);
    __syncthreads();

    const float* xb = x + (size_t)b * SS * DD + (size_t)h * 256 * DD;
    float a0 = 0.f, a1 = 0.f, a2 = 0.f, a3 = 0.f;
    #pragma unroll 2
    for (int s = 0; s < 256; s += 4) {
        a0 = fmaf(xb[(size_t)(s + 0) * DD + t], w[s + 0], a0);
        a1 = fmaf(xb[(size_t)(s + 1) * DD + t], w[s + 1], a1);
        a2 = fmaf(xb[(size_t)(s + 2) * DD + t], w[s + 2], a2);
        a3 = fmaf(xb[(size_t)(s + 3) * DD + t], w[s + 3], a3);
    }
    g_part[(b * 2 + h) * DD + t] = ((a0 + a1) + (a2 + a3)) * inv;
}

// out[b,d] = part[b,0,d] + part[b,1,d]
__global__ void __launch_bounds__(256)
combine_kernel(float* __restrict__ out)
{
    const int b = blockIdx.x;
    const int t = threadIdx.x;
    out[b * DD + t] = g_part[(b * 2) * DD + t] + g_part[(b * 2 + 1) * DD + t];
}

extern "C" void kernel_launch(void* const* d_in, const int* in_sizes, int n_in,
                              void* d_out, int out_size)
{
    const float* x    = (const float*)d_in[0];   // [B,S,D]
    const float* W    = (const float*)d_in[1];   // [D,AT]
    const float* bias = (const float*)d_in[2];   // [AT]
    const float* u    = (const float*)d_in[3];   // [AT,1]
    float* out        = (float*)d_out;           // [B,D]

    (void)in_sizes; (void)n_in; (void)out_size;

    scores_kernel<<<(BB * SS) / TM, NTHREADS>>>(x, W, bias, u);
    output_partial_kernel<<<BB * 2, 256>>>(x);
    combine_kernel<<<BB, 256>>>(out);
}